// round 1
// baseline (speedup 1.0000x reference)
#include <cuda_runtime.h>
#include <math.h>

// Problem constants (fixed shapes per reference)
#define BATCH 16
#define CH    3
#define H     512
#define W     512
#define WS    11
#define PAD   5

// Tiling
#define TX    64
#define TY    32
#define TXH   76            // TX + 2*PAD padded to multiple of 4 for float4
#define TYH   (TY + 2*PAD)  // 42
#define NTHREADS 256
#define HB    (TYH * TX)    // per-field hbuf size (floats)

struct GW { float w[WS]; };

__device__ double g_num;
__device__ double g_den;

__global__ void zero_acc_kernel() { g_num = 0.0; g_den = 0.0; }

__global__ void finalize_kernel(float* out) {
    out[0] = (float)(g_num / g_den / 3.0);
}

extern __shared__ float smem[];

__global__ __launch_bounds__(NTHREADS) void ssim_kernel(
    const float* __restrict__ img1,
    const float* __restrict__ img2,
    const float* __restrict__ match,
    GW gw)
{
    // Shared layout
    float* raw1  = smem;                      // TYH*TXH
    float* raw2  = raw1 + TYH * TXH;          // TYH*TXH
    float* hbuf  = raw2 + TYH * TXH;          // 5 * TYH * TX
    float* maskb = hbuf + 5 * HB;             // TY*TX

    const int tid = threadIdx.x;
    const int x0 = blockIdx.x * TX;
    const int y0 = blockIdx.y * TY;
    const int b  = blockIdx.z;

    float lnum = 0.f;
    float lden = 0.f;

    // ======================= mask pass (box filter on match) =======================
    {
        const float* mp = match + (size_t)b * H * W;
        for (int i = tid; i < TYH * TXH; i += NTHREADS) {
            int y = i / TXH, x = i - y * TXH;
            int gy = y0 + y - PAD, gx = x0 + x - PAD;
            float v = 0.f;
            if ((unsigned)gy < H && (unsigned)gx < W) v = mp[gy * W + gx];
            raw1[i] = v;
        }
        __syncthreads();
        // horizontal box sum
        for (int i = tid; i < TYH * TX; i += NTHREADS) {
            int x = i & (TX - 1);
            int y = i >> 6;
            const float* r = raw1 + y * TXH + x;
            float s = 0.f;
            #pragma unroll
            for (int k = 0; k < WS; k++) s += r[k];
            hbuf[i] = s;
        }
        __syncthreads();
        // vertical box sum + threshold
        for (int i = tid; i < TY * TX; i += NTHREADS) {
            int x = i & (TX - 1);
            int y = i >> 6;
            float s = 0.f;
            #pragma unroll
            for (int k = 0; k < WS; k++) s += hbuf[(y + k) * TX + x];
            float m = s * (1.0f / 121.0f) + 1e-07f;
            float mv = (m > 0.5f) ? (1.0f + 1e-07f) : 1e-07f;
            maskb[i] = mv;
            lden += mv;
        }
        __syncthreads();
    }

    // ======================= per-channel SSIM =======================
    for (int c = 0; c < CH; c++) {
        const float* p1 = img1 + ((size_t)b * CH + c) * H * W;
        const float* p2 = img2 + ((size_t)b * CH + c) * H * W;

        // load halo tiles
        for (int i = tid; i < TYH * TXH; i += NTHREADS) {
            int y = i / TXH, x = i - y * TXH;
            int gy = y0 + y - PAD, gx = x0 + x - PAD;
            float v1 = 0.f, v2 = 0.f;
            if ((unsigned)gy < H && (unsigned)gx < W) {
                int gi = gy * W + gx;
                v1 = p1[gi];
                v2 = p2[gi];
            }
            raw1[i] = v1;
            raw2[i] = v2;
        }
        __syncthreads();

        // -------- horizontal Gaussian pass: 5 fields, R=4 outputs/thread, float4 loads
        // items: TYH rows x (TX/4) column groups = 42*16 = 672
        for (int i = tid; i < TYH * (TX / 4); i += NTHREADS) {
            int xg = i & 15;      // column group (xg*4 .. xg*4+3)
            int y  = i >> 4;
            const float4* r1 = (const float4*)(raw1 + y * TXH) + xg;
            const float4* r2 = (const float4*)(raw2 + y * TXH) + xg;
            float v1[16], v2[16];
            #pragma unroll
            for (int q = 0; q < 4; q++) {
                float4 a4 = r1[q];
                float4 b4 = r2[q];
                v1[4*q+0] = a4.x; v1[4*q+1] = a4.y; v1[4*q+2] = a4.z; v1[4*q+3] = a4.w;
                v2[4*q+0] = b4.x; v2[4*q+1] = b4.y; v2[4*q+2] = b4.z; v2[4*q+3] = b4.w;
            }
            float A[4]  = {0,0,0,0};
            float Bv[4] = {0,0,0,0};
            float AA[4] = {0,0,0,0};
            float BB[4] = {0,0,0,0};
            float AB[4] = {0,0,0,0};
            #pragma unroll
            for (int k = 0; k < WS; k++) {
                float w = gw.w[k];
                #pragma unroll
                for (int r = 0; r < 4; r++) {
                    float x1 = v1[k + r];
                    float x2 = v2[k + r];
                    float w1 = w * x1;
                    float w2 = w * x2;
                    A[r]  += w1;
                    Bv[r] += w2;
                    AA[r] = fmaf(w1, x1, AA[r]);
                    BB[r] = fmaf(w2, x2, BB[r]);
                    AB[r] = fmaf(w1, x2, AB[r]);
                }
            }
            int o = y * TX + xg * 4;
            *(float4*)(hbuf + 0 * HB + o) = make_float4(A[0],  A[1],  A[2],  A[3]);
            *(float4*)(hbuf + 1 * HB + o) = make_float4(Bv[0], Bv[1], Bv[2], Bv[3]);
            *(float4*)(hbuf + 2 * HB + o) = make_float4(AA[0], AA[1], AA[2], AA[3]);
            *(float4*)(hbuf + 3 * HB + o) = make_float4(BB[0], BB[1], BB[2], BB[3]);
            *(float4*)(hbuf + 4 * HB + o) = make_float4(AB[0], AB[1], AB[2], AB[3]);
        }
        __syncthreads();

        // -------- vertical Gaussian pass + SSIM: R=4 outputs/thread along y
        // items: (TY/4) y-groups x TX = 8*64 = 512
        for (int i = tid; i < (TY / 4) * TX; i += NTHREADS) {
            int x  = i & (TX - 1);
            int yg = i >> 6;
            int yb = yg * 4;
            float M1[4]  = {0,0,0,0};
            float M2[4]  = {0,0,0,0};
            float E11[4] = {0,0,0,0};
            float E22[4] = {0,0,0,0};
            float E12[4] = {0,0,0,0};
            #pragma unroll
            for (int k = 0; k < WS + 3; k++) {  // 14 shared rows serve 4 outputs
                int off = (yb + k) * TX + x;
                float h0 = hbuf[0 * HB + off];
                float h1 = hbuf[1 * HB + off];
                float h2 = hbuf[2 * HB + off];
                float h3 = hbuf[3 * HB + off];
                float h4 = hbuf[4 * HB + off];
                #pragma unroll
                for (int r = 0; r < 4; r++) {
                    int kk = k - r;
                    if (kk >= 0 && kk < WS) {
                        float w = gw.w[kk];
                        M1[r]  = fmaf(w, h0, M1[r]);
                        M2[r]  = fmaf(w, h1, M2[r]);
                        E11[r] = fmaf(w, h2, E11[r]);
                        E22[r] = fmaf(w, h3, E22[r]);
                        E12[r] = fmaf(w, h4, E12[r]);
                    }
                }
            }
            const float C1 = 1e-4f;
            const float C2 = 9e-4f;
            #pragma unroll
            for (int r = 0; r < 4; r++) {
                float mu1sq = M1[r] * M1[r];
                float mu2sq = M2[r] * M2[r];
                float mu12  = M1[r] * M2[r];
                float s11 = E11[r] - mu1sq;
                float s22 = E22[r] - mu2sq;
                float s12 = E12[r] - mu12;
                float numer = (2.f * mu12 + C1) * (2.f * s12 + C2);
                float denom = (mu1sq + mu2sq + C1) * (s11 + s22 + C2);
                float ssim = numer / denom;
                lnum += (1.f - ssim) * maskb[(yb + r) * TX + x];
            }
        }
        __syncthreads();
    }

    // ======================= block reduction + global atomics =======================
    const unsigned full = 0xffffffffu;
    #pragma unroll
    for (int o = 16; o > 0; o >>= 1) {
        lnum += __shfl_down_sync(full, lnum, o);
        lden += __shfl_down_sync(full, lden, o);
    }
    __shared__ float red[16];
    int wid = tid >> 5, lane = tid & 31;
    if (lane == 0) { red[wid] = lnum; red[wid + 8] = lden; }
    __syncthreads();
    if (tid == 0) {
        float n = 0.f, d = 0.f;
        #pragma unroll
        for (int i = 0; i < 8; i++) { n += red[i]; d += red[i + 8]; }
        atomicAdd(&g_num, (double)n);
        atomicAdd(&g_den, (double)d);
    }
}

static GW make_weights() {
    GW g;
    double gg[WS], s = 0.0;
    for (int i = 0; i < WS; i++) {
        double d = (double)i - (double)(WS / 2);
        gg[i] = exp(-(d * d) / (2.0 * 1.5 * 1.5));
        s += gg[i];
    }
    for (int i = 0; i < WS; i++) g.w[i] = (float)(gg[i] / s);
    return g;
}

#define SMEM_BYTES ((2 * TYH * TXH + 5 * HB + TY * TX) * (int)sizeof(float))

extern "C" void kernel_launch(void* const* d_in, const int* in_sizes, int n_in,
                              void* d_out, int out_size) {
    const float* img1  = (const float*)d_in[0];
    const float* img2  = (const float*)d_in[1];
    const float* match = (const float*)d_in[2];

    GW gw = make_weights();

    cudaFuncSetAttribute(ssim_kernel,
                         cudaFuncAttributeMaxDynamicSharedMemorySize, SMEM_BYTES);

    zero_acc_kernel<<<1, 1>>>();
    dim3 grid(W / TX, H / TY, BATCH);
    ssim_kernel<<<grid, NTHREADS, SMEM_BYTES>>>(img1, img2, match, gw);
    finalize_kernel<<<1, 1>>>((float*)d_out);
}